// round 12
// baseline (speedup 1.0000x reference)
#include <cuda_runtime.h>
#include <cstdint>

#define FNUM 50
#define DDIM 16
#define ADIM 32
#define TPB  256
#define ESTR 20                  // padded e-row stride (floats); float4-aligned
#define EROWS 52                 // 50 real rows + 2 zero pad rows
#define NRB  13                  // 4-row blocks covering 0..51
#define NB   91                  // blocks (ri, cj) with 0 <= ri <= cj <= 12
#define NSLOT (NB * 16)          // 1456 score slots (incl. masked invalids)

typedef unsigned int u32;

// Split x into bf16 hi + bf16 lo, two values packed per bf16x2 register.
__device__ __forceinline__ void split_bf16x2(float x0, float x1, u32& hi, u32& lo) {
    asm("cvt.rn.bf16x2.f32 %0, %1, %2;" : "=r"(hi) : "f"(x1), "f"(x0));
    float h0 = __uint_as_float(hi << 16);
    float h1 = __uint_as_float(hi & 0xFFFF0000u);
    float r0 = x0 - h0;
    float r1 = x1 - h1;
    asm("cvt.rn.bf16x2.f32 %0, %1, %2;" : "=r"(lo) : "f"(r1), "f"(r0));
}
__device__ __forceinline__ void mma_bf16(float* c, const u32* a, const u32* b) {
    asm volatile(
        "mma.sync.aligned.m16n8k16.row.col.f32.bf16.bf16.f32 "
        "{%0,%1,%2,%3}, {%4,%5,%6,%7}, {%8,%9}, {%0,%1,%2,%3};"
        : "+f"(c[0]), "+f"(c[1]), "+f"(c[2]), "+f"(c[3])
        : "r"(a[0]), "r"(a[1]), "r"(a[2]), "r"(a[3]), "r"(b[0]), "r"(b[1]));
}

__global__ __launch_bounds__(TPB) void afm_kernel(
    const float* __restrict__ feat,   // [B, F, D]
    const float* __restrict__ Wg,     // [D, A] row-major
    const float* __restrict__ hg,     // [A]
    const float* __restrict__ pvg,    // [D]
    float* __restrict__ out)          // [B]
{
    __shared__ __align__(16) float s_e[EROWS * ESTR];
    __shared__ float s_score[NSLOT];
    __shared__ float s_t[NSLOT];
    __shared__ unsigned short s_blk[NB + 1];   // ri | (cj<<8)
    __shared__ float s_red[24];

    const int tid  = threadIdx.x;
    const int b    = blockIdx.x;
    const int lane = tid & 31;
    const int wid  = tid >> 5;
    const int g    = lane >> 2;      // C-row group 0..7
    const int m    = lane & 3;       // k-slice / C-col pair

    // ---- SMEM fill: features (padded stride, 2 zero rows), block table ----
    {
        const float* src = feat + (size_t)b * (FNUM * DDIM);
        #pragma unroll 1
        for (int i = tid; i < FNUM * DDIM; i += TPB) {
            int r = i >> 4, d = i & 15;
            s_e[r * ESTR + d] = src[i];
        }
    }
    if (tid < 2 * ESTR) s_e[FNUM * ESTR + tid] = 0.f;   // rows 50, 51 = 0
    if (tid < NRB) {
        int ri   = tid;
        int base = ri * NRB - (ri * (ri - 1)) / 2;
        int cnt  = NRB - ri;
        for (int k = 0; k < cnt; ++k)
            s_blk[base + k] = (unsigned short)(ri | ((ri + k) << 8));
    }

    // ---- B fragments (registers), K-permuted: lane m's memory d-slice is
    //      contiguous 4m..4m+3 ----
    u32 bh[4][2], bl[4][2];
    #pragma unroll
    for (int nt = 0; nt < 4; ++nt) {
        const int n = nt * 8 + g;
        split_bf16x2(Wg[(4 * m)     * ADIM + n], Wg[(4 * m + 1) * ADIM + n],
                     bh[nt][0], bl[nt][0]);
        split_bf16x2(Wg[(4 * m + 2) * ADIM + n], Wg[(4 * m + 3) * ADIM + n],
                     bh[nt][1], bl[nt][1]);
    }
    float hreg[8];
    #pragma unroll
    for (int nt = 0; nt < 4; ++nt) {
        hreg[2 * nt]     = hg[nt * 8 + 2 * m];
        hreg[2 * nt + 1] = hg[nt * 8 + 2 * m + 1];
    }
    const float4 pvr = *(const float4*)(pvg + 4 * m);
    __syncthreads();

    // ---- main loop: one 4x4 feature block (16 pair slots) per warp-iter ----
    // slot s (0..15): feature pair (4*ri + (s>>2), 4*cj + (s&3)).
    // MMA C-row g  -> slot g   (lr = g>>2,     lc = g&3)
    // MMA C-row g+8-> slot g+8 (lr = (g>>2)+2, lc = g&3)
    #pragma unroll 1
    for (int blk = wid; blk < NB; blk += TPB / 32) {
        const unsigned bw = s_blk[blk];
        const int ri4 = (bw & 0xFF) * 4;
        const int cj4 = (bw >> 8) * 4;
        const int rA  = ri4 + (g >> 2);      // pair-0 row
        const int rB  = rA + 2;              // pair-1 row
        const int cc  = cj4 + (g & 3);       // shared col-feature row

        // 3 vectorized e-loads (heavy intra-warp broadcast)
        const float4 ea = *(const float4*)(s_e + rA * ESTR + 4 * m);
        const float4 eb = *(const float4*)(s_e + rB * ESTR + 4 * m);
        const float4 fc = *(const float4*)(s_e + cc * ESTR + 4 * m);

        float x0[4], x1[4];
        x0[0] = ea.x * fc.x;  x0[1] = ea.y * fc.y;
        x0[2] = ea.z * fc.z;  x0[3] = ea.w * fc.w;
        x1[0] = eb.x * fc.x;  x1[1] = eb.y * fc.y;
        x1[2] = eb.z * fc.z;  x1[3] = eb.w * fc.w;

        u32 ah[4], al[4];
        split_bf16x2(x0[0], x0[1], ah[0], al[0]);
        split_bf16x2(x1[0], x1[1], ah[1], al[1]);
        split_bf16x2(x0[2], x0[3], ah[2], al[2]);
        split_bf16x2(x1[2], x1[3], ah[3], al[3]);

        float acc[4][4];
        #pragma unroll
        for (int nt = 0; nt < 4; ++nt) {
            acc[nt][0] = 0.f; acc[nt][1] = 0.f; acc[nt][2] = 0.f; acc[nt][3] = 0.f;
        }

        // 3-pass split product: hi*hi + hi*lo + lo*hi
        #pragma unroll
        for (int nt = 0; nt < 4; ++nt) mma_bf16(acc[nt], ah, bh[nt]);
        #pragma unroll
        for (int nt = 0; nt < 4; ++nt) mma_bf16(acc[nt], ah, bl[nt]);
        #pragma unroll
        for (int nt = 0; nt < 4; ++nt) mma_bf16(acc[nt], al, bh[nt]);

        // scalar t partials (full fp32)
        float t0 = x0[0] * pvr.x;
        t0 = fmaf(x0[1], pvr.y, t0);
        t0 = fmaf(x0[2], pvr.z, t0);
        t0 = fmaf(x0[3], pvr.w, t0);
        float t1 = x1[0] * pvr.x;
        t1 = fmaf(x1[1], pvr.y, t1);
        t1 = fmaf(x1[2], pvr.z, t1);
        t1 = fmaf(x1[3], pvr.w, t1);

        // epilogue: relu + h-dot
        float s0 = 0.f, s1 = 0.f;
        #pragma unroll
        for (int nt = 0; nt < 4; ++nt) {
            s0 = fmaf(fmaxf(acc[nt][0], 0.f), hreg[2 * nt],     s0);
            s0 = fmaf(fmaxf(acc[nt][1], 0.f), hreg[2 * nt + 1], s0);
            s1 = fmaf(fmaxf(acc[nt][2], 0.f), hreg[2 * nt],     s1);
            s1 = fmaf(fmaxf(acc[nt][3], 0.f), hreg[2 * nt + 1], s1);
        }

        // quad reductions across m
        s0 += __shfl_xor_sync(0xffffffffu, s0, 1);
        s0 += __shfl_xor_sync(0xffffffffu, s0, 2);
        s1 += __shfl_xor_sync(0xffffffffu, s1, 1);
        s1 += __shfl_xor_sync(0xffffffffu, s1, 2);
        t0 += __shfl_xor_sync(0xffffffffu, t0, 1);
        t0 += __shfl_xor_sync(0xffffffffu, t0, 2);
        t1 += __shfl_xor_sync(0xffffffffu, t1, 1);
        t1 += __shfl_xor_sync(0xffffffffu, t1, 2);

        if (m == 0) {
            const bool v0 = (rA < cc) && (cc < FNUM);
            const bool v1 = (rB < cc) && (cc < FNUM);
            const int base = blk * 16 + g;
            s_score[base]     = v0 ? s0 : -3.4e38f;
            s_t[base]         = v0 ? t0 : 0.f;
            s_score[base + 8] = v1 ? s1 : -3.4e38f;
            s_t[base + 8]     = v1 ? t1 : 0.f;
        }
    }

    __syncthreads();

    // ---- fused softmax reduction over all slots (masked slots -> exp 0) ----
    float mx = -3.4e38f;
    for (int p = tid; p < NSLOT; p += TPB) mx = fmaxf(mx, s_score[p]);
    #pragma unroll
    for (int o = 16; o > 0; o >>= 1) mx = fmaxf(mx, __shfl_xor_sync(0xffffffffu, mx, o));
    if (lane == 0) s_red[wid] = mx;
    __syncthreads();

    float mm = s_red[0];
    #pragma unroll
    for (int i = 1; i < 8; ++i) mm = fmaxf(mm, s_red[i]);

    float se = 0.f, st = 0.f;
    for (int p = tid; p < NSLOT; p += TPB) {
        float e = __expf(s_score[p] - mm);
        se += e;
        st = fmaf(e, s_t[p], st);
    }
    #pragma unroll
    for (int o = 16; o > 0; o >>= 1) {
        se += __shfl_xor_sync(0xffffffffu, se, o);
        st += __shfl_xor_sync(0xffffffffu, st, o);
    }
    if (lane == 0) { s_red[8 + wid] = se; s_red[16 + wid] = st; }
    __syncthreads();

    if (tid == 0) {
        float SE = 0.f, ST = 0.f;
        #pragma unroll
        for (int i = 0; i < 8; ++i) { SE += s_red[8 + i]; ST += s_red[16 + i]; }
        out[b] = ST / SE;
    }
}

extern "C" void kernel_launch(void* const* d_in, const int* in_sizes, int n_in,
                              void* d_out, int out_size) {
    const float* feat = (const float*)d_in[0];   // [B, 50, 16]
    const float* W    = (const float*)d_in[1];   // [16, 32]
    const float* h    = (const float*)d_in[2];   // [32]
    const float* pv   = (const float*)d_in[3];   // [16]
    float* out        = (float*)d_out;           // [B, 1]

    const int B = in_sizes[0] / (FNUM * DDIM);   // 4096
    afm_kernel<<<B, TPB>>>(feat, W, h, pv, out);
}

// round 15
// speedup vs baseline: 1.1336x; 1.1336x over previous
#include <cuda_runtime.h>
#include <cstdint>

#define FNUM 50
#define DDIM 16
#define ADIM 32
#define NP   1225
#define NPAD 1232                // 77 tiles of 16
#define MT   77
#define TPB  256
#define ESTR 20                  // padded e-row stride (floats); float4-aligned

typedef unsigned int u32;

// Split x into bf16 hi + bf16 lo, two values packed per bf16x2 register.
// reg = {lo16 = bf16(x0), hi16 = bf16(x1)}  (MMA fragment order: even elem low).
__device__ __forceinline__ void split_bf16x2(float x0, float x1, u32& hi, u32& lo) {
    asm("cvt.rn.bf16x2.f32 %0, %1, %2;" : "=r"(hi) : "f"(x1), "f"(x0));
    float h0 = __uint_as_float(hi << 16);
    float h1 = __uint_as_float(hi & 0xFFFF0000u);
    float r0 = x0 - h0;
    float r1 = x1 - h1;
    asm("cvt.rn.bf16x2.f32 %0, %1, %2;" : "=r"(lo) : "f"(r1), "f"(r0));
}
__device__ __forceinline__ void mma_bf16(float* c, const u32* a, const u32* b) {
    asm volatile(
        "mma.sync.aligned.m16n8k16.row.col.f32.bf16.bf16.f32 "
        "{%0,%1,%2,%3}, {%4,%5,%6,%7}, {%8,%9}, {%0,%1,%2,%3};"
        : "+f"(c[0]), "+f"(c[1]), "+f"(c[2]), "+f"(c[3])
        : "r"(a[0]), "r"(a[1]), "r"(a[2]), "r"(a[3]), "r"(b[0]), "r"(b[1]));
}

__global__ __launch_bounds__(TPB) void afm_kernel(
    const float* __restrict__ feat,   // [B, F, D]
    const float* __restrict__ Wg,     // [D, A] row-major
    const float* __restrict__ hg,     // [A]
    const float* __restrict__ pvg,    // [D]
    float* __restrict__ out)          // [B]
{
    __shared__ __align__(16) float s_e[FNUM * ESTR];
    __shared__ __align__(8) float2 s_st[NP];   // {score, t} interleaved
    __shared__ unsigned short s_pair[NPAD];    // row | (col<<8)
    __shared__ float s_red[24];

    const int tid  = threadIdx.x;
    const int b    = blockIdx.x;
    const int lane = tid & 31;
    const int wid  = tid >> 5;
    const int g    = lane >> 2;      // A/C row group, B col
    const int m    = lane & 3;       // thread-in-group

    // ---- SMEM fill: features (padded stride), packed triu table ----
    {
        const float* src = feat + (size_t)b * (FNUM * DDIM);
        #pragma unroll 1
        for (int i = tid; i < FNUM * DDIM; i += TPB) {
            int r = i >> 4, d = i & 15;
            s_e[r * ESTR + d] = src[i];
        }
    }
    if (tid < FNUM - 1) {
        int r    = tid;
        int base = r * (FNUM - 1) - (r * (r - 1)) / 2;
        int cnt  = FNUM - 1 - r;
        for (int k = 0; k < cnt; ++k)
            s_pair[base + k] = (unsigned short)(r | ((r + 1 + k) << 8));
    }
    if (tid < NPAD - NP) s_pair[NP + tid] = (unsigned short)(0 | (1 << 8));

    // ---- B fragments (registers), K-permuted so this lane's memory d-slice
    //      is contiguous 4m..4m+3:
    //      b[nt][0] = {W[4m][n], W[4m+1][n]},  b[nt][1] = {W[4m+2][n], W[4m+3][n]}
    u32 bh[4][2], bl[4][2];
    #pragma unroll
    for (int nt = 0; nt < 4; ++nt) {
        const int n = nt * 8 + g;
        split_bf16x2(Wg[(4 * m)     * ADIM + n], Wg[(4 * m + 1) * ADIM + n],
                     bh[nt][0], bl[nt][0]);
        split_bf16x2(Wg[(4 * m + 2) * ADIM + n], Wg[(4 * m + 3) * ADIM + n],
                     bh[nt][1], bl[nt][1]);
    }
    // t-tile B fragments: column 0 = p_vec (lanes with g==0 supply it), rest 0
    u32 bth[2] = {0u, 0u}, btl[2] = {0u, 0u};
    if (g == 0) {
        split_bf16x2(pvg[4 * m],     pvg[4 * m + 1], bth[0], btl[0]);
        split_bf16x2(pvg[4 * m + 2], pvg[4 * m + 3], bth[1], btl[1]);
    }
    // h slice for epilogue: cols nt*8 + 2m, +1  (N not permuted)
    float hreg[8];
    #pragma unroll
    for (int nt = 0; nt < 4; ++nt) {
        hreg[2 * nt]     = hg[nt * 8 + 2 * m];
        hreg[2 * nt + 1] = hg[nt * 8 + 2 * m + 1];
    }
    __syncthreads();

    // ---- main loop: one M-tile (16 pairs) per warp-iteration ----
    #pragma unroll 1
    for (int mt = wid; mt < MT; mt += TPB / 32) {
        const int p0 = mt * 16 + g;
        const int p1 = p0 + 8;
        const unsigned pr0 = s_pair[p0];
        const unsigned pr1 = s_pair[p1];
        const int r0 = pr0 & 0xFF, q0 = pr0 >> 8;
        const int r1 = pr1 & 0xFF, q1 = pr1 >> 8;

        // vectorized e-row loads: this lane's 4 contiguous d = 4m..4m+3
        const float4 ea = *(const float4*)(s_e + r0 * ESTR + 4 * m);
        const float4 fa = *(const float4*)(s_e + q0 * ESTR + 4 * m);
        const float4 eb = *(const float4*)(s_e + r1 * ESTR + 4 * m);
        const float4 fb = *(const float4*)(s_e + q1 * ESTR + 4 * m);

        // raw products (memory d-order)
        float x0[4], x1[4];
        x0[0] = ea.x * fa.x;  x0[1] = ea.y * fa.y;
        x0[2] = ea.z * fa.z;  x0[3] = ea.w * fa.w;
        x1[0] = eb.x * fb.x;  x1[1] = eb.y * fb.y;
        x1[2] = eb.z * fb.z;  x1[3] = eb.w * fb.w;

        // A fragments m16n8k16 (bf16x2 regs)
        u32 ah[4], al[4];
        split_bf16x2(x0[0], x0[1], ah[0], al[0]);
        split_bf16x2(x1[0], x1[1], ah[1], al[1]);
        split_bf16x2(x0[2], x0[3], ah[2], al[2]);
        split_bf16x2(x1[2], x1[3], ah[3], al[3]);

        float acc[4][4];
        #pragma unroll
        for (int nt = 0; nt < 4; ++nt) {
            acc[nt][0] = 0.f; acc[nt][1] = 0.f; acc[nt][2] = 0.f; acc[nt][3] = 0.f;
        }
        float acct[4] = {0.f, 0.f, 0.f, 0.f};   // t-tile accumulator

        // 3-pass split product: hi*hi + hi*lo + lo*hi  (lo*lo ~2^-18, dropped)
        #pragma unroll
        for (int nt = 0; nt < 4; ++nt) mma_bf16(acc[nt], ah, bh[nt]);
        mma_bf16(acct, ah, bth);
        #pragma unroll
        for (int nt = 0; nt < 4; ++nt) mma_bf16(acc[nt], ah, bl[nt]);
        mma_bf16(acct, ah, btl);
        #pragma unroll
        for (int nt = 0; nt < 4; ++nt) mma_bf16(acc[nt], al, bh[nt]);
        mma_bf16(acct, al, bth);

        // epilogue: relu + h-dot
        float s0 = 0.f, s1 = 0.f;
        #pragma unroll
        for (int nt = 0; nt < 4; ++nt) {
            s0 = fmaf(fmaxf(acc[nt][0], 0.f), hreg[2 * nt],     s0);
            s0 = fmaf(fmaxf(acc[nt][1], 0.f), hreg[2 * nt + 1], s0);
            s1 = fmaf(fmaxf(acc[nt][2], 0.f), hreg[2 * nt],     s1);
            s1 = fmaf(fmaxf(acc[nt][3], 0.f), hreg[2 * nt + 1], s1);
        }

        // quad reductions across m (scores only; t comes from the MMA at m==0)
        s0 += __shfl_xor_sync(0xffffffffu, s0, 1);
        s0 += __shfl_xor_sync(0xffffffffu, s0, 2);
        s1 += __shfl_xor_sync(0xffffffffu, s1, 1);
        s1 += __shfl_xor_sync(0xffffffffu, s1, 2);

        if (m == 0) {
            // t-tile column 0 lives in c[0] (row p0) / c[2] (row p1) of lane m==0
            if (p0 < NP) s_st[p0] = make_float2(s0, acct[0]);
            if (p1 < NP) s_st[p1] = make_float2(s1, acct[2]);
        }
    }

    __syncthreads();

    // ---- fused softmax reduction: out[b] = sum(e*t) / sum(e) ----
    float mx = -3.4e38f;
    for (int p = tid; p < NP; p += TPB) mx = fmaxf(mx, s_st[p].x);
    #pragma unroll
    for (int o = 16; o > 0; o >>= 1) mx = fmaxf(mx, __shfl_xor_sync(0xffffffffu, mx, o));
    if (lane == 0) s_red[wid] = mx;
    __syncthreads();

    float mm = s_red[0];
    #pragma unroll
    for (int i = 1; i < 8; ++i) mm = fmaxf(mm, s_red[i]);

    float se = 0.f, st = 0.f;
    for (int p = tid; p < NP; p += TPB) {
        float2 v = s_st[p];
        float e = __expf(v.x - mm);
        se += e;
        st = fmaf(e, v.y, st);
    }
    #pragma unroll
    for (int o = 16; o > 0; o >>= 1) {
        se += __shfl_xor_sync(0xffffffffu, se, o);
        st += __shfl_xor_sync(0xffffffffu, st, o);
    }
    if (lane == 0) { s_red[8 + wid] = se; s_red[16 + wid] = st; }
    __syncthreads();

    if (tid == 0) {
        float SE = 0.f, ST = 0.f;
        #pragma unroll
        for (int i = 0; i < 8; ++i) { SE += s_red[8 + i]; ST += s_red[16 + i]; }
        out[b] = ST / SE;
    }
}

extern "C" void kernel_launch(void* const* d_in, const int* in_sizes, int n_in,
                              void* d_out, int out_size) {
    const float* feat = (const float*)d_in[0];   // [B, 50, 16]
    const float* W    = (const float*)d_in[1];   // [16, 32]
    const float* h    = (const float*)d_in[2];   // [32]
    const float* pv   = (const float*)d_in[3];   // [16]
    float* out        = (float*)d_out;           // [B, 1]

    const int B = in_sizes[0] / (FNUM * DDIM);   // 4096
    afm_kernel<<<B, TPB>>>(feat, W, h, pv, out);
}

// round 17
// speedup vs baseline: 1.1951x; 1.0543x over previous
#include <cuda_runtime.h>
#include <cstdint>

#define FNUM 50
#define DDIM 16
#define ADIM 32
#define NP   1225
#define NPAD 1232                // 77 tiles of 16
#define MT   77
#define TPB  256
#define ESTR 20                  // padded e-row stride (floats); float4-aligned

typedef unsigned int u32;

// Split x into bf16 hi + bf16 lo, two values packed per bf16x2 register.
__device__ __forceinline__ void split_bf16x2(float x0, float x1, u32& hi, u32& lo) {
    asm("cvt.rn.bf16x2.f32 %0, %1, %2;" : "=r"(hi) : "f"(x1), "f"(x0));
    float h0 = __uint_as_float(hi << 16);
    float h1 = __uint_as_float(hi & 0xFFFF0000u);
    float r0 = x0 - h0;
    float r1 = x1 - h1;
    asm("cvt.rn.bf16x2.f32 %0, %1, %2;" : "=r"(lo) : "f"(r1), "f"(r0));
}
__device__ __forceinline__ void mma_bf16(float* c, const u32* a, const u32* b) {
    asm volatile(
        "mma.sync.aligned.m16n8k16.row.col.f32.bf16.bf16.f32 "
        "{%0,%1,%2,%3}, {%4,%5,%6,%7}, {%8,%9}, {%0,%1,%2,%3};"
        : "+f"(c[0]), "+f"(c[1]), "+f"(c[2]), "+f"(c[3])
        : "r"(a[0]), "r"(a[1]), "r"(a[2]), "r"(a[3]), "r"(b[0]), "r"(b[1]));
}

__global__ __launch_bounds__(TPB, 2) void afm_kernel(
    const float* __restrict__ feat,   // [B, F, D]
    const float* __restrict__ Wg,     // [D, A] row-major
    const float* __restrict__ hg,     // [A]
    const float* __restrict__ pvg,    // [D]
    float* __restrict__ out)          // [B]
{
    __shared__ __align__(16) float s_e[2][FNUM * ESTR];
    __shared__ __align__(8) float2 s_st[2][NP];   // {score, t} per batch
    __shared__ unsigned short s_pair[NPAD];       // row | (col<<8)
    __shared__ float s_red[48];

    const int tid  = threadIdx.x;
    const int lane = tid & 31;
    const int wid  = tid >> 5;
    const int g    = lane >> 2;      // A/C row group, B col
    const int m    = lane & 3;       // thread-in-group

    // ---- SMEM fill: 2 batches of features (contiguous in gmem), triu table ----
    {
        const float* src = feat + (size_t)(2 * blockIdx.x) * (FNUM * DDIM);
        #pragma unroll 1
        for (int i = tid; i < 2 * FNUM * DDIM; i += TPB) {
            int bi = (i >= FNUM * DDIM);
            int j  = i - bi * (FNUM * DDIM);
            int r  = j >> 4, d = j & 15;
            s_e[bi][r * ESTR + d] = src[i];
        }
    }
    if (tid < FNUM - 1) {
        int r    = tid;
        int base = r * (FNUM - 1) - (r * (r - 1)) / 2;
        int cnt  = FNUM - 1 - r;
        for (int k = 0; k < cnt; ++k)
            s_pair[base + k] = (unsigned short)(r | ((r + 1 + k) << 8));
    }
    if (tid < NPAD - NP) s_pair[NP + tid] = (unsigned short)(0 | (1 << 8));

    // ---- B fragments (registers), K-permuted: lane m's d-slice = 4m..4m+3 ----
    u32 bh[4][2], bl[4][2];
    #pragma unroll
    for (int nt = 0; nt < 4; ++nt) {
        const int n = nt * 8 + g;
        split_bf16x2(Wg[(4 * m)     * ADIM + n], Wg[(4 * m + 1) * ADIM + n],
                     bh[nt][0], bl[nt][0]);
        split_bf16x2(Wg[(4 * m + 2) * ADIM + n], Wg[(4 * m + 3) * ADIM + n],
                     bh[nt][1], bl[nt][1]);
    }
    // t-tile B fragments: column 0 = p_vec (g==0 lanes), rest 0
    u32 bth[2] = {0u, 0u}, btl[2] = {0u, 0u};
    if (g == 0) {
        split_bf16x2(pvg[4 * m],     pvg[4 * m + 1], bth[0], btl[0]);
        split_bf16x2(pvg[4 * m + 2], pvg[4 * m + 3], bth[1], btl[1]);
    }
    float hreg[8];
    #pragma unroll
    for (int nt = 0; nt < 4; ++nt) {
        hreg[2 * nt]     = hg[nt * 8 + 2 * m];
        hreg[2 * nt + 1] = hg[nt * 8 + 2 * m + 1];
    }
    __syncthreads();

    // ---- main loop: one M-tile for BOTH batches per warp-iteration ----
    #pragma unroll 1
    for (int mt = wid; mt < MT; mt += TPB / 32) {
        const int p0 = mt * 16 + g;
        const int p1 = p0 + 8;
        const unsigned pr0 = s_pair[p0];
        const unsigned pr1 = s_pair[p1];
        const int oR0 = (pr0 & 0xFF) * ESTR + 4 * m;
        const int oQ0 = (pr0 >> 8)   * ESTR + 4 * m;
        const int oR1 = (pr1 & 0xFF) * ESTR + 4 * m;
        const int oQ1 = (pr1 >> 8)   * ESTR + 4 * m;

        // e-loads for both batches (same offsets, different base)
        const float4 ea0 = *(const float4*)(s_e[0] + oR0);
        const float4 fa0 = *(const float4*)(s_e[0] + oQ0);
        const float4 eb0 = *(const float4*)(s_e[0] + oR1);
        const float4 fb0 = *(const float4*)(s_e[0] + oQ1);
        const float4 ea1 = *(const float4*)(s_e[1] + oR0);
        const float4 fa1 = *(const float4*)(s_e[1] + oQ0);
        const float4 eb1 = *(const float4*)(s_e[1] + oR1);
        const float4 fb1 = *(const float4*)(s_e[1] + oQ1);

        // A fragments for both batches
        u32 ah0[4], al0[4], ah1[4], al1[4];
        split_bf16x2(ea0.x * fa0.x, ea0.y * fa0.y, ah0[0], al0[0]);
        split_bf16x2(eb0.x * fb0.x, eb0.y * fb0.y, ah0[1], al0[1]);
        split_bf16x2(ea0.z * fa0.z, ea0.w * fa0.w, ah0[2], al0[2]);
        split_bf16x2(eb0.z * fb0.z, eb0.w * fb0.w, ah0[3], al0[3]);
        split_bf16x2(ea1.x * fa1.x, ea1.y * fa1.y, ah1[0], al1[0]);
        split_bf16x2(eb1.x * fb1.x, eb1.y * fb1.y, ah1[1], al1[1]);
        split_bf16x2(ea1.z * fa1.z, ea1.w * fa1.w, ah1[2], al1[2]);
        split_bf16x2(eb1.z * fb1.z, eb1.w * fb1.w, ah1[3], al1[3]);

        float acc0[4][4], acc1[4][4];
        #pragma unroll
        for (int nt = 0; nt < 4; ++nt)
            #pragma unroll
            for (int e = 0; e < 4; ++e) { acc0[nt][e] = 0.f; acc1[nt][e] = 0.f; }
        float acct0[4] = {0.f, 0.f, 0.f, 0.f};
        float acct1[4] = {0.f, 0.f, 0.f, 0.f};

        // 3-pass split product, batches interleaved for ILP
        #pragma unroll
        for (int nt = 0; nt < 4; ++nt) { mma_bf16(acc0[nt], ah0, bh[nt]); mma_bf16(acc1[nt], ah1, bh[nt]); }
        mma_bf16(acct0, ah0, bth);  mma_bf16(acct1, ah1, bth);
        #pragma unroll
        for (int nt = 0; nt < 4; ++nt) { mma_bf16(acc0[nt], ah0, bl[nt]); mma_bf16(acc1[nt], ah1, bl[nt]); }
        mma_bf16(acct0, ah0, btl);  mma_bf16(acct1, ah1, btl);
        #pragma unroll
        for (int nt = 0; nt < 4; ++nt) { mma_bf16(acc0[nt], al0, bh[nt]); mma_bf16(acc1[nt], al1, bh[nt]); }
        mma_bf16(acct0, al0, bth);  mma_bf16(acct1, al1, bth);

        // epilogues: relu + h-dot
        float s00 = 0.f, s01 = 0.f, s10 = 0.f, s11 = 0.f;
        #pragma unroll
        for (int nt = 0; nt < 4; ++nt) {
            s00 = fmaf(fmaxf(acc0[nt][0], 0.f), hreg[2 * nt],     s00);
            s00 = fmaf(fmaxf(acc0[nt][1], 0.f), hreg[2 * nt + 1], s00);
            s01 = fmaf(fmaxf(acc0[nt][2], 0.f), hreg[2 * nt],     s01);
            s01 = fmaf(fmaxf(acc0[nt][3], 0.f), hreg[2 * nt + 1], s01);
            s10 = fmaf(fmaxf(acc1[nt][0], 0.f), hreg[2 * nt],     s10);
            s10 = fmaf(fmaxf(acc1[nt][1], 0.f), hreg[2 * nt + 1], s10);
            s11 = fmaf(fmaxf(acc1[nt][2], 0.f), hreg[2 * nt],     s11);
            s11 = fmaf(fmaxf(acc1[nt][3], 0.f), hreg[2 * nt + 1], s11);
        }

        // quad reductions across m
        s00 += __shfl_xor_sync(0xffffffffu, s00, 1);
        s00 += __shfl_xor_sync(0xffffffffu, s00, 2);
        s01 += __shfl_xor_sync(0xffffffffu, s01, 1);
        s01 += __shfl_xor_sync(0xffffffffu, s01, 2);
        s10 += __shfl_xor_sync(0xffffffffu, s10, 1);
        s10 += __shfl_xor_sync(0xffffffffu, s10, 2);
        s11 += __shfl_xor_sync(0xffffffffu, s11, 1);
        s11 += __shfl_xor_sync(0xffffffffu, s11, 2);

        if (m == 0) {
            if (p0 < NP) { s_st[0][p0] = make_float2(s00, acct0[0]);
                           s_st[1][p0] = make_float2(s10, acct1[0]); }
            if (p1 < NP) { s_st[0][p1] = make_float2(s01, acct0[2]);
                           s_st[1][p1] = make_float2(s11, acct1[2]); }
        }
    }

    __syncthreads();

    // ---- fused softmax for both batches: out = sum(e*t)/sum(e) ----
    float mx0 = -3.4e38f, mx1 = -3.4e38f;
    for (int p = tid; p < NP; p += TPB) {
        mx0 = fmaxf(mx0, s_st[0][p].x);
        mx1 = fmaxf(mx1, s_st[1][p].x);
    }
    #pragma unroll
    for (int o = 16; o > 0; o >>= 1) {
        mx0 = fmaxf(mx0, __shfl_xor_sync(0xffffffffu, mx0, o));
        mx1 = fmaxf(mx1, __shfl_xor_sync(0xffffffffu, mx1, o));
    }
    if (lane == 0) { s_red[wid] = mx0; s_red[8 + wid] = mx1; }
    __syncthreads();

    float mm0 = s_red[0], mm1 = s_red[8];
    #pragma unroll
    for (int i = 1; i < 8; ++i) {
        mm0 = fmaxf(mm0, s_red[i]);
        mm1 = fmaxf(mm1, s_red[8 + i]);
    }

    float se0 = 0.f, st0 = 0.f, se1 = 0.f, st1 = 0.f;
    for (int p = tid; p < NP; p += TPB) {
        float2 v0 = s_st[0][p];
        float2 v1 = s_st[1][p];
        float e0 = __expf(v0.x - mm0);
        float e1 = __expf(v1.x - mm1);
        se0 += e0;  st0 = fmaf(e0, v0.y, st0);
        se1 += e1;  st1 = fmaf(e1, v1.y, st1);
    }
    #pragma unroll
    for (int o = 16; o > 0; o >>= 1) {
        se0 += __shfl_xor_sync(0xffffffffu, se0, o);
        st0 += __shfl_xor_sync(0xffffffffu, st0, o);
        se1 += __shfl_xor_sync(0xffffffffu, se1, o);
        st1 += __shfl_xor_sync(0xffffffffu, st1, o);
    }
    if (lane == 0) {
        s_red[16 + wid] = se0;  s_red[24 + wid] = st0;
        s_red[32 + wid] = se1;  s_red[40 + wid] = st1;
    }
    __syncthreads();

    if (tid == 0) {
        float SE0 = 0.f, ST0 = 0.f, SE1 = 0.f, ST1 = 0.f;
        #pragma unroll
        for (int i = 0; i < 8; ++i) {
            SE0 += s_red[16 + i];  ST0 += s_red[24 + i];
            SE1 += s_red[32 + i];  ST1 += s_red[40 + i];
        }
        out[2 * blockIdx.x]     = ST0 / SE0;
        out[2 * blockIdx.x + 1] = ST1 / SE1;
    }
}

extern "C" void kernel_launch(void* const* d_in, const int* in_sizes, int n_in,
                              void* d_out, int out_size) {
    const float* feat = (const float*)d_in[0];   // [B, 50, 16]
    const float* W    = (const float*)d_in[1];   // [16, 32]
    const float* h    = (const float*)d_in[2];   // [32]
    const float* pv   = (const float*)d_in[3];   // [16]
    float* out        = (float*)d_out;           // [B, 1]

    const int B = in_sizes[0] / (FNUM * DDIM);   // 4096
    afm_kernel<<<B / 2, TPB>>>(feat, W, h, pv, out);
}